// round 1
// baseline (speedup 1.0000x reference)
#include <cuda_runtime.h>
#include <cstdint>

// Problem constants
#define D_EMBED 64
#define NUM_K   512
#define N_ROWS  131072          // 32*64*64

// Output layout (floats), concatenated in reference-return order:
//   quantized [131072*64], perplexity [1], encodings [131072*512],
//   encoding_indices [131072], distances [131072*512]
#define OFF_QUANT 0ULL
#define OFF_PERP  8388608ULL
#define OFF_ENC   8388609ULL
#define OFF_IDX   75497473ULL
#define OFF_DIST  75628545ULL

// Dynamic smem: cbT[64][512] (transposed codebook) + cnorm[512]
#define SMEM_FLOATS (D_EMBED * NUM_K + NUM_K)
#define SMEM_BYTES  (SMEM_FLOATS * 4)

__device__ int g_hist[NUM_K];

__device__ __forceinline__ void ffma2(uint64_t& acc, uint64_t a, uint64_t b) {
    asm("fma.rn.f32x2 %0, %1, %2, %0;" : "+l"(acc) : "l"(a), "l"(b));
}

__global__ void vq_zero_hist() {
    g_hist[threadIdx.x] = 0;
}

__global__ __launch_bounds__(256, 1)
void vq_main(const float* __restrict__ inp,
             const float* __restrict__ cb,
             float* __restrict__ out) {
    extern __shared__ float smem[];
    float* cbT   = smem;                    // [d][k], k contiguous
    float* cnorm = smem + D_EMBED * NUM_K;  // [k]

    // Load codebook transposed: read gathered (L2-hot after wave 1),
    // write conflict-free (consecutive threads -> consecutive k).
    for (int i = threadIdx.x; i < NUM_K * D_EMBED; i += 256) {
        int k = i & (NUM_K - 1);
        int d = i >> 9;
        cbT[d * NUM_K + k] = cb[k * D_EMBED + d];
    }
    __syncthreads();

    // Per-CTA codebook norms (cheap: 512 values)
    for (int k = threadIdx.x; k < NUM_K; k += 256) {
        float s = 0.0f;
        #pragma unroll
        for (int d = 0; d < D_EMBED; ++d) {
            float v = cbT[d * NUM_K + k];
            s += v * v;
        }
        cnorm[k] = s;
    }
    __syncthreads();

    const int row = blockIdx.x * 256 + threadIdx.x;   // grid exactly covers N_ROWS

    // Row into registers + ||x||^2
    float x[D_EMBED];
    float xnorm = 0.0f;
    const float4* xin = reinterpret_cast<const float4*>(inp + (size_t)row * D_EMBED);
    #pragma unroll
    for (int i = 0; i < 16; ++i) {
        float4 v = xin[i];
        x[4 * i + 0] = v.x; x[4 * i + 1] = v.y;
        x[4 * i + 2] = v.z; x[4 * i + 3] = v.w;
        xnorm += v.x * v.x + v.y * v.y + v.z * v.z + v.w * v.w;
    }

    float best = 3.4e38f;
    int   bidx = 0;
    float* dist_out = out + OFF_DIST + (size_t)row * NUM_K;
    float* enc_out  = out + OFF_ENC  + (size_t)row * NUM_K;

    for (int k0 = 0; k0 < NUM_K; k0 += 16) {
        uint64_t acc[8];
        #pragma unroll
        for (int j = 0; j < 8; ++j) acc[j] = 0ULL;

        const float* cbase = cbT + k0;
        #pragma unroll
        for (int d = 0; d < D_EMBED; ++d) {
            uint32_t xi = __float_as_uint(x[d]);
            uint64_t xv;
            asm("mov.b64 %0, {%1, %1};" : "=l"(xv) : "r"(xi));
            const ulonglong2* cp =
                reinterpret_cast<const ulonglong2*>(cbase + d * NUM_K);
            ulonglong2 c0 = cp[0];
            ulonglong2 c1 = cp[1];
            ulonglong2 c2 = cp[2];
            ulonglong2 c3 = cp[3];
            ffma2(acc[0], xv, c0.x); ffma2(acc[1], xv, c0.y);
            ffma2(acc[2], xv, c1.x); ffma2(acc[3], xv, c1.y);
            ffma2(acc[4], xv, c2.x); ffma2(acc[5], xv, c2.y);
            ffma2(acc[6], xv, c3.x); ffma2(acc[7], xv, c3.y);
        }

        // distances + argmin (ascending k, strict < -> first-min like jnp.argmin)
        #pragma unroll
        for (int j = 0; j < 8; ++j) {
            float dot0 = __uint_as_float((uint32_t)(acc[j] & 0xFFFFFFFFULL));
            float dot1 = __uint_as_float((uint32_t)(acc[j] >> 32));
            int k = k0 + 2 * j;
            float dv0 = xnorm - 2.0f * dot0 + cnorm[k];
            float dv1 = xnorm - 2.0f * dot1 + cnorm[k + 1];
            dist_out[k]     = dv0;
            dist_out[k + 1] = dv1;
            enc_out[k]      = 0.0f;   // zero-fill one-hot row (fused)
            enc_out[k + 1]  = 0.0f;
            if (dv0 < best) { best = dv0; bidx = k; }
            if (dv1 < best) { best = dv1; bidx = k + 1; }
        }
    }

    // One-hot (thread-local ordering after the zeros above is guaranteed)
    enc_out[bidx] = 1.0f;
    out[OFF_IDX + row] = (float)bidx;

    // quantized = codebook[bidx] (straight-through forward value)
    float4* qout = reinterpret_cast<float4*>(out + OFF_QUANT + (size_t)row * D_EMBED);
    #pragma unroll
    for (int i = 0; i < 16; ++i) {
        float4 v;
        v.x = cbT[(4 * i + 0) * NUM_K + bidx];
        v.y = cbT[(4 * i + 1) * NUM_K + bidx];
        v.z = cbT[(4 * i + 2) * NUM_K + bidx];
        v.w = cbT[(4 * i + 3) * NUM_K + bidx];
        qout[i] = v;
    }

    atomicAdd(&g_hist[bidx], 1);
}

__global__ void vq_perplexity(float* __restrict__ out) {
    __shared__ float red[NUM_K];
    int t = threadIdx.x;
    float p = (float)g_hist[t] * (1.0f / (float)N_ROWS);
    red[t] = p * logf(p + 1e-10f);
    __syncthreads();
    for (int s = NUM_K / 2; s > 0; s >>= 1) {
        if (t < s) red[t] += red[t + s];
        __syncthreads();
    }
    if (t == 0) out[OFF_PERP] = expf(-red[0]);
}

extern "C" void kernel_launch(void* const* d_in, const int* in_sizes, int n_in,
                              void* d_out, int out_size) {
    const float* inp = (const float*)d_in[0];   // [32,64,64,64]
    const float* cb  = (const float*)d_in[1];   // [512,64]
    float* out = (float*)d_out;

    cudaFuncSetAttribute(vq_main, cudaFuncAttributeMaxDynamicSharedMemorySize,
                         SMEM_BYTES);

    vq_zero_hist<<<1, NUM_K>>>();
    vq_main<<<N_ROWS / 256, 256, SMEM_BYTES>>>(inp, cb, out);
    vq_perplexity<<<1, NUM_K>>>(out);
}

// round 4
// speedup vs baseline: 3.0133x; 3.0133x over previous
#include <cuda_runtime.h>
#include <cstdint>

// Problem constants
#define D_EMBED 64
#define NUM_K   512
#define N_ROWS  131072              // 32*64*64

// Output layout (floats), reference-return order:
//   quantized [131072*64], perplexity [1], encodings [131072*512],
//   encoding_indices [131072], distances [131072*512]
// NOTE: OFF_ENC and OFF_DIST are ODD -> enc/dist rows are only 4B-aligned.
//       All stores to them must be STG.32.
#define OFF_QUANT 0ULL
#define OFF_PERP  8388608ULL
#define OFF_ENC   8388609ULL
#define OFF_IDX   75497473ULL
#define OFF_DIST  75628545ULL

#define CBT_STRIDE 516              // floats; %4==0 (16B alignment), conflict-free quads
#define XS_STRIDE  36              // floats per d-pair block (8 rows * 4 floats + pad)
#define ROWS_PER_WARP 8
#define WARPS_PER_CTA 8
#define ROWS_PER_CTA  (ROWS_PER_WARP * WARPS_PER_CTA)   // 64
#define GRID_MAIN     (N_ROWS / ROWS_PER_CTA)           // 2048

// smem: cbT[64][516] + cnorm[512] + xs[8 warps][32 dp][36]
#define SMEM_CBT_FLOATS (D_EMBED * CBT_STRIDE)          // 33024
#define SMEM_CN_OFF     SMEM_CBT_FLOATS
#define SMEM_XS_OFF     (SMEM_CN_OFF + NUM_K)           // 33536
#define XS_PER_WARP     (32 * XS_STRIDE)                // 1152 (>= 512: reused as stage)
#define SMEM_FLOATS     (SMEM_XS_OFF + WARPS_PER_CTA * XS_PER_WARP)
#define SMEM_BYTES      (SMEM_FLOATS * 4)               // 171,008 B

__device__ float g_cbT[D_EMBED * NUM_K];   // transposed codebook [d][k]
__device__ float g_cnorm[NUM_K];
__device__ int   g_hist[NUM_K];
__device__ unsigned int g_ticket;

__device__ __forceinline__ void ffma2(uint64_t& acc, uint64_t a, uint64_t b) {
    asm("fma.rn.f32x2 %0, %1, %2, %0;" : "+l"(acc) : "l"(a), "l"(b));
}
__device__ __forceinline__ uint64_t fma2v(uint64_t a, uint64_t b, uint64_t c) {
    uint64_t d;
    asm("fma.rn.f32x2 %0, %1, %2, %3;" : "=l"(d) : "l"(a), "l"(b), "l"(c));
    return d;
}
__device__ __forceinline__ uint64_t add2(uint64_t a, uint64_t b) {
    uint64_t d;
    asm("add.rn.f32x2 %0, %1, %2;" : "=l"(d) : "l"(a), "l"(b));
    return d;
}
__device__ __forceinline__ uint64_t pack2(float f) {
    uint64_t d; uint32_t r = __float_as_uint(f);
    asm("mov.b64 %0, {%1, %1};" : "=l"(d) : "r"(r));
    return d;
}
__device__ __forceinline__ void unpack2(uint64_t v, float& lo, float& hi) {
    uint32_t a, b;
    asm("mov.b64 {%0, %1}, %2;" : "=r"(a), "=r"(b) : "l"(v));
    lo = __uint_as_float(a); hi = __uint_as_float(b);
}

// One small block: transpose codebook to gmem, codebook norms, zero hist/ticket.
__global__ void vq_prep(const float* __restrict__ cb) {
    int t = threadIdx.x;            // 512 threads, t == k
    g_hist[t] = 0;
    if (t == 0) g_ticket = 0;
    float s = 0.0f;
    #pragma unroll
    for (int d = 0; d < D_EMBED; ++d) {
        float v = cb[t * D_EMBED + d];
        g_cbT[d * NUM_K + t] = v;       // coalesced writes
        s += v * v;
    }
    g_cnorm[t] = s;
}

__global__ __launch_bounds__(256, 1)
void vq_main(const float* __restrict__ inp,
             const float* __restrict__ cb,
             float* __restrict__ out) {
    extern __shared__ float smem[];
    float* cbT   = smem;
    float* cnorm = smem + SMEM_CN_OFF;
    float* xs    = smem + SMEM_XS_OFF;

    const int tid  = threadIdx.x;
    const int warp = tid >> 5;
    const int lane = tid & 31;

    // ---- Fill cbT (coalesced LDG, conflict-free STS, stride 516) ----
    {
        const float4* src = reinterpret_cast<const float4*>(g_cbT);
        for (int i = tid; i < D_EMBED * NUM_K / 4; i += 256) {
            int d  = i >> 7;            // 128 float4 per d-row
            int k4 = (i & 127) << 2;
            *reinterpret_cast<float4*>(cbT + d * CBT_STRIDE + k4) = src[i];
        }
        const float4* cs = reinterpret_cast<const float4*>(g_cnorm);
        for (int i = tid; i < NUM_K / 4; i += 256)
            reinterpret_cast<float4*>(cnorm)[i] = cs[i];
    }

    // ---- Stage this warp's 8 rows as duplicated f32 pairs xs[dp][4r + 2h] ----
    const size_t rowBase = (size_t)blockIdx.x * ROWS_PER_CTA + warp * ROWS_PER_WARP;
    float* xsw = xs + warp * XS_PER_WARP;
    {
        const float4* xin = reinterpret_cast<const float4*>(inp + rowBase * D_EMBED);
        #pragma unroll
        for (int m = 0; m < 4; ++m) {
            int i = lane + 32 * m;          // 128 float4 per warp
            float4 v = xin[i];
            int r = i >> 4;                 // row 0..7
            int c = i & 15;                 // d0 = 4c
            float* b0 = xsw + (2 * c) * XS_STRIDE + 4 * r;
            float* b1 = xsw + (2 * c + 1) * XS_STRIDE + 4 * r;
            *reinterpret_cast<uint64_t*>(b0)     = pack2(v.x);
            *reinterpret_cast<uint64_t*>(b0 + 2) = pack2(v.y);
            *reinterpret_cast<uint64_t*>(b1)     = pack2(v.z);
            *reinterpret_cast<uint64_t*>(b1 + 2) = pack2(v.w);
        }
    }
    __syncthreads();

    // ---- Row norms (lanes 0..7), broadcast to all lanes ----
    float xn_l = 0.0f;
    if (lane < 8) {
        #pragma unroll
        for (int d = 0; d < D_EMBED; ++d) {
            float v = xsw[(d >> 1) * XS_STRIDE + 4 * lane + 2 * (d & 1)];
            xn_l += v * v;
        }
    }
    float xn[ROWS_PER_WARP];
    #pragma unroll
    for (int r = 0; r < ROWS_PER_WARP; ++r)
        xn[r] = __shfl_sync(0xffffffffu, xn_l, r);

    // ---- Main loop: lane owns k = 4*lane + 128*j (+0..3), j = 0..3 ----
    uint64_t acc[ROWS_PER_WARP][8];
    #pragma unroll
    for (int r = 0; r < ROWS_PER_WARP; ++r)
        #pragma unroll
        for (int j = 0; j < 8; ++j) acc[r][j] = 0ULL;

    #pragma unroll 4
    for (int dp = 0; dp < 32; ++dp) {
        ulonglong2 c0[4], c1[4];
        const ulonglong2* p0 = reinterpret_cast<const ulonglong2*>(
            cbT + (2 * dp) * CBT_STRIDE + 4 * lane);
        const ulonglong2* p1 = reinterpret_cast<const ulonglong2*>(
            cbT + (2 * dp + 1) * CBT_STRIDE + 4 * lane);
        #pragma unroll
        for (int j = 0; j < 4; ++j) { c0[j] = p0[32 * j]; c1[j] = p1[32 * j]; }

        #pragma unroll
        for (int r = 0; r < ROWS_PER_WARP; ++r) {
            ulonglong2 xv = *reinterpret_cast<const ulonglong2*>(
                xsw + dp * XS_STRIDE + 4 * r);   // {x[2dp],x[2dp]},{x[2dp+1],x[2dp+1]}
            #pragma unroll
            for (int j = 0; j < 4; ++j) {
                ffma2(acc[r][2 * j],     xv.x, c0[j].x);
                ffma2(acc[r][2 * j + 1], xv.x, c0[j].y);
                ffma2(acc[r][2 * j],     xv.y, c1[j].x);
                ffma2(acc[r][2 * j + 1], xv.y, c1[j].y);
            }
        }
    }

    // ---- Epilogue: distances, argmin, outputs ----
    // xs region is dead now; reuse this warp's slice as a 512-float stage.
    float* stage = xsw;
    ulonglong2 cn[4];
    #pragma unroll
    for (int j = 0; j < 4; ++j)
        cn[j] = *reinterpret_cast<const ulonglong2*>(cnorm + 4 * lane + 128 * j);
    const uint64_t m2 = pack2(-2.0f);
    __syncwarp();

    #pragma unroll
    for (int r = 0; r < ROWS_PER_WARP; ++r) {
        const size_t row = rowBase + r;
        const uint64_t xn2 = pack2(xn[r]);
        float best = 3.4e38f;
        int bidx = 0;

        #pragma unroll
        for (int j = 0; j < 4; ++j) {
            uint64_t dA = add2(fma2v(acc[r][2 * j],     m2, xn2), cn[j].x);
            uint64_t dB = add2(fma2v(acc[r][2 * j + 1], m2, xn2), cn[j].y);
            float f0, f1, f2, f3;
            unpack2(dA, f0, f1);
            unpack2(dB, f2, f3);
            int kb = 4 * lane + 128 * j;
            // conflict-free STS.128 into the per-warp stage
            *reinterpret_cast<float4*>(stage + kb) = make_float4(f0, f1, f2, f3);
            if (f0 < best) { best = f0; bidx = kb; }
            if (f1 < best) { best = f1; bidx = kb + 1; }
            if (f2 < best) { best = f2; bidx = kb + 2; }
            if (f3 < best) { best = f3; bidx = kb + 3; }
        }
        // warp argmin (value, then smallest index on ties -> first occurrence)
        #pragma unroll
        for (int o = 16; o > 0; o >>= 1) {
            float v2 = __shfl_xor_sync(0xffffffffu, best, o);
            int   i2 = __shfl_xor_sync(0xffffffffu, bidx, o);
            if (v2 < best || (v2 == best && i2 < bidx)) { best = v2; bidx = i2; }
        }
        __syncwarp();

        // Coalesced STG.32 sweeps (base is odd -> scalar stores mandatory).
        float* dptr = out + OFF_DIST + row * NUM_K;
        float* eptr = out + OFF_ENC  + row * NUM_K;
        #pragma unroll
        for (int j = 0; j < 16; ++j) {
            int k = lane + 32 * j;
            dptr[k] = stage[k];                     // LDS.32 + STG.32, coalesced
            eptr[k] = (k == bidx) ? 1.0f : 0.0f;    // STG.32, coalesced
        }
        __syncwarp();   // protect stage before next r overwrites

        // quantized row (16B-aligned region -> float4 OK; codebook L2-resident)
        if (lane < 16) {
            float4 q = *reinterpret_cast<const float4*>(cb + bidx * D_EMBED + 4 * lane);
            *reinterpret_cast<float4*>(out + OFF_QUANT + row * D_EMBED + 4 * lane) = q;
        }
        if (lane == 0) {
            out[OFF_IDX + row] = (float)bidx;
            atomicAdd(&g_hist[bidx], 1);
        }
    }

    // ---- Last CTA computes perplexity ----
    __shared__ unsigned int s_ticket;
    __threadfence();
    __syncthreads();
    if (tid == 0) s_ticket = atomicAdd(&g_ticket, 1u);
    __syncthreads();
    if (s_ticket == (unsigned)(gridDim.x - 1)) {
        float part = 0.0f;
        for (int k = tid; k < NUM_K; k += 256) {
            float p = (float)g_hist[k] * (1.0f / (float)N_ROWS);
            part += p * logf(p + 1e-10f);
        }
        smem[tid] = part;
        __syncthreads();
        for (int s = 128; s > 0; s >>= 1) {
            if (tid < s) smem[tid] += smem[tid + s];
            __syncthreads();
        }
        if (tid == 0) out[OFF_PERP] = expf(-smem[0]);
    }
}

extern "C" void kernel_launch(void* const* d_in, const int* in_sizes, int n_in,
                              void* d_out, int out_size) {
    const float* inp = (const float*)d_in[0];   // [32,64,64,64]
    const float* cb  = (const float*)d_in[1];   // [512,64]
    float* out = (float*)d_out;

    cudaFuncSetAttribute(vq_main, cudaFuncAttributeMaxDynamicSharedMemorySize,
                         SMEM_BYTES);

    vq_prep<<<1, NUM_K>>>(cb);
    vq_main<<<GRID_MAIN, 256, SMEM_BYTES>>>(inp, cb, out);
}